// round 1
// baseline (speedup 1.0000x reference)
#include <cuda_runtime.h>

typedef unsigned long long ull;

// ---------------- packed f32x2 helpers (Blackwell FFMA2 path) ----------------
__device__ __forceinline__ ull pack2(float a, float b) {
    ull r; asm("mov.b64 %0, {%1,%2};" : "=l"(r) : "f"(a), "f"(b)); return r;
}
__device__ __forceinline__ float2 unpack2(ull v) {
    float2 f; asm("mov.b64 {%0,%1}, %2;" : "=f"(f.x), "=f"(f.y) : "l"(v)); return f;
}
__device__ __forceinline__ ull ffma2(ull a, ull b, ull c) {
    ull d; asm("fma.rn.f32x2 %0, %1, %2, %3;" : "=l"(d) : "l"(a), "l"(b), "l"(c)); return d;
}
__device__ __forceinline__ ull fadd2(ull a, ull b) {
    ull d; asm("add.rn.f32x2 %0, %1, %2;" : "=l"(d) : "l"(a), "l"(b)); return d;
}

__device__ __forceinline__ float sigmoidf_fast(float x) {
    return __fdividef(1.f, 1.f + __expf(-x));
}
__device__ __forceinline__ float tanhf_fast(float x) {
    // tanh(x) = 1 - 2/(exp(2x)+1); robust at both tails with __expf saturation
    return 1.f - 2.f * __fdividef(1.f, __expf(2.f * x) + 1.f);
}

#define B_  256
#define S_  1024
#define F_  64
#define H_  64
#define G_  256   // 4*H

// Scratch: xz[t][b][pair j] packed as (col j, col j+128). 1024*256*128 * 8B = 268MB.
__device__ ull g_xz[(size_t)S_ * B_ * 128];

// =====================================================================
// Kernel A: xz = x @ kernel + bias   (input-projection GEMM, FFMA2)
// Grid: 1024 CTAs x 256 thr. Each CTA: 64 iterations x 4 (b,t)-rows.
// Thread layout: j = tid&127 owns gate-column pair (j, j+128);
//                half = tid>>7 selects which 2 of the 4 rows it computes.
// =====================================================================
__global__ void __launch_bounds__(256, 1) lstm_xgemm(
    const float* __restrict__ x, const float* __restrict__ kern,
    const float* __restrict__ bias)
{
    const int tid  = threadIdx.x;
    const int j    = tid & 127;
    const int half = tid >> 7;

    // Kernel columns (j, j+128) packed, in registers: 64 x 64-bit
    ull wk[64];
#pragma unroll
    for (int k = 0; k < 64; k++)
        wk[k] = pack2(kern[k * G_ + j], kern[k * G_ + 128 + j]);
    const ull bj = pack2(bias[j], bias[j + 128]);

    __shared__ __align__(16) ull xdup[2][4][64];   // x values duplicated into both lanes

    const int lr = tid >> 6;   // 0..3 : which row this thread loads
    const int lk = tid & 63;   // which feature

    const int qbase = blockIdx.x * 64;             // 64 quads (of 4 rows) per CTA

    float v = x[(size_t)(qbase * 4 + lr) * F_ + lk];   // prefetch iter 0
    int buf = 0;
    for (int i = 0; i < 64; i++) {
        xdup[buf][lr][lk] = pack2(v, v);
        __syncthreads();
        if (i + 1 < 64)
            v = x[(size_t)((qbase + i + 1) * 4 + lr) * F_ + lk];  // prefetch next

        const ull* xa = xdup[buf][half];       // row n0
        const ull* xb = xdup[buf][half + 2];   // row n0+2
        ull a0 = bj, a0b = 0ull, a1 = bj, a1b = 0ull;
#pragma unroll
        for (int k = 0; k < 64; k += 2) {
            a0  = ffma2(wk[k],     xa[k],     a0);
            a0b = ffma2(wk[k + 1], xa[k + 1], a0b);
            a1  = ffma2(wk[k],     xb[k],     a1);
            a1b = ffma2(wk[k + 1], xb[k + 1], a1b);
        }
        const ull r0 = fadd2(a0, a0b);
        const ull r1 = fadd2(a1, a1b);

        const int n0 = (qbase + i) * 4 + half;   // global row index = b*S + t
        const int n1 = n0 + 2;
        {
            const int bb = n0 >> 10, tt = n0 & 1023;
            g_xz[((size_t)tt * B_ + bb) * 128 + j] = r0;
        }
        {
            const int bb = n1 >> 10, tt = n1 & 1023;
            g_xz[((size_t)tt * B_ + bb) * 128 + j] = r1;
        }
        buf ^= 1;
    }
}

// =====================================================================
// Kernel B: sequential LSTM recurrence + fused dense head.
// Grid: 128 CTAs x 256 thr. CTA handles 2 batch rows.
//   tid = r*128 + j : r = local row, j = gate-column pair (j, j+128).
//   Pairing: j<64  -> (z_i[j],  z_c[j])
//            j>=64 -> (z_f[j-64], z_o[j-64])
// Gate phase: warps 0,1,4,5 (j<64) update c,h.
// Output phase (overlapped): warp 2 -> row0, warp 6 -> row1 compute
//   out(t-1) = sigmoid(h(t-1)·dw + db) while gate warps write h(t)
//   into the OTHER parity buffer (double-buffered h).
// =====================================================================
__global__ void __launch_bounds__(256, 1) lstm_recur(
    const float* __restrict__ rec, const float* __restrict__ dw,
    const float* __restrict__ db, float* __restrict__ out)
{
    const int tid  = threadIdx.x;
    const int j    = tid & 127;
    const int r    = tid >> 7;
    const int brow = blockIdx.x * 2 + r;

    // Recurrent weight column pair (j, j+128), packed, in registers
    ull wr[64];
#pragma unroll
    for (int k = 0; k < 64; k++)
        wr[k] = pack2(rec[k * G_ + j], rec[k * G_ + 128 + j]);

    __shared__ __align__(16) ull hdup[2][2][64];  // [parity][row][k], h duplicated in lanes
    __shared__ float2 zbuf[2][128];               // [row][pair]

    if (tid < 128) hdup[1][tid >> 6][tid & 63] = 0ull;  // h(-1) = 0 at parity 1

    const int  wid    = tid >> 5;
    const int  lane   = tid & 31;
    const bool isGate = (j < 64);
    const bool isOut  = (wid == 2) | (wid == 6);
    const int  orow   = (wid == 6) ? 1 : 0;
    const int  obrow  = blockIdx.x * 2 + orow;

    float c = 0.f;
    const float dwa   = dw[lane];
    const float dwb   = dw[lane + 32];
    const float dbias = db[0];

    const ull*   zp = g_xz + (size_t)brow * 128 + j;
    const size_t ZS = (size_t)B_ * 128;

    ull z0 = zp[0];        // depth-2 z prefetch pipeline
    ull z1 = zp[ZS];
    __syncthreads();

    for (int t = 0; t < S_; t++) {
        ull acc0 = z0;                       // z-input (loaded 2 steps ago)
        z0 = z1;
        if (t + 2 < S_) z1 = zp[(size_t)(t + 2) * ZS];

        const int  pr = (t & 1) ^ 1;         // parity holding h(t-1)
        const ull* hp = hdup[pr][r];
        ull acc1 = 0ull;
#pragma unroll
        for (int k = 0; k < 64; k += 2) {
            acc0 = ffma2(wr[k],     hp[k],     acc0);
            acc1 = ffma2(wr[k + 1], hp[k + 1], acc1);
        }
        zbuf[r][j] = unpack2(fadd2(acc0, acc1));
        __syncthreads();

        if (isGate) {
            const float2 a  = zbuf[r][j];        // (z_i, z_c)
            const float2 bq = zbuf[r][64 + j];   // (z_f, z_o)
            const float ig = sigmoidf_fast(a.x);
            const float fg = sigmoidf_fast(bq.x);
            const float og = sigmoidf_fast(bq.y);
            c = fg * c + ig * tanhf_fast(a.y);
            const float h = og * tanhf_fast(c);
            hdup[t & 1][r][j] = pack2(h, h);     // write h(t) to parity t&1
        } else if (isOut && t > 0) {
            // out(t-1) from h(t-1) at parity pr — disjoint from gate writes
            const ull* hh = hdup[pr][orow];
            float p = unpack2(hh[lane]).x * dwa + unpack2(hh[lane + 32]).x * dwb;
#pragma unroll
            for (int off = 16; off; off >>= 1)
                p += __shfl_xor_sync(0xffffffffu, p, off);
            if (lane == 0)
                out[(size_t)obrow * S_ + (t - 1)] = sigmoidf_fast(p + dbias);
        }
        __syncthreads();
    }

    // Final output: h(S-1) lives at parity (S-1)&1 = 1
    if (isOut) {
        const ull* hh = hdup[1][orow];
        float p = unpack2(hh[lane]).x * dwa + unpack2(hh[lane + 32]).x * dwb;
#pragma unroll
        for (int off = 16; off; off >>= 1)
            p += __shfl_xor_sync(0xffffffffu, p, off);
        if (lane == 0)
            out[(size_t)obrow * S_ + (S_ - 1)] = sigmoidf_fast(p + dbias);
    }
}

// =====================================================================
extern "C" void kernel_launch(void* const* d_in, const int* in_sizes, int n_in,
                              void* d_out, int out_size)
{
    const float* x    = (const float*)d_in[0];  // [256,1024,64]
    const float* kern = (const float*)d_in[1];  // [64,256]
    const float* rec  = (const float*)d_in[2];  // [64,256]
    const float* bias = (const float*)d_in[3];  // [256]
    const float* dw   = (const float*)d_in[4];  // [64,1]
    const float* db   = (const float*)d_in[5];  // [1]
    float* out = (float*)d_out;                 // [256,1024,1]

    lstm_xgemm<<<1024, 256>>>(x, kern, bias);
    lstm_recur<<<128, 256>>>(rec, dw, db, out);
}